// round 16
// baseline (speedup 1.0000x reference)
#include <cuda_runtime.h>
#include <cuda_bf16.h>
#include <stdint.h>
#include <math.h>

// Problem constants
#define B_TOTAL 8192
#define T_STEPS 60
#define F_IN    158
#define HDIM    32
#define G4      128
#define NBLK    128                        // 64-row blocks

typedef unsigned long long u64;
typedef ulonglong2 u64x2;

// ---------------- helpers ----------------
__device__ __forceinline__ void ffma2(u64 &acc, u64 a, u64 b) {
    asm("fma.rn.f32x2 %0, %1, %2, %0;" : "+l"(acc) : "l"(a), "l"(b));
}
__device__ __forceinline__ u64 pack2(float x, float y) {
    u64 r; asm("mov.b64 %0, {%1, %2};" : "=l"(r) : "f"(x), "f"(y)); return r;
}
__device__ __forceinline__ u64 pack2s(float x) {
    u64 r; asm("mov.b64 %0, {%1, %1};" : "=l"(r) : "f"(x)); return r;
}
__device__ __forceinline__ float2 unpack2(u64 v) {
    float2 r; asm("mov.b64 {%0, %1}, %2;" : "=f"(r.x), "=f"(r.y) : "l"(v)); return r;
}
__device__ __forceinline__ float tanha(float x) {
    float y; asm("tanh.approx.f32 %0, %1;" : "=f"(y) : "f"(x)); return y;
}
__device__ __forceinline__ float sigf(float x) {      // 0.5*tanh(x/2)+0.5
    return fmaf(0.5f, tanha(0.5f * x), 0.5f);
}
__device__ __forceinline__ void split_pair(float2 v, uint32_t &hw, uint32_t &lw) {
    __nv_bfloat16 h0 = __float2bfloat16(v.x);
    __nv_bfloat16 h1 = __float2bfloat16(v.y);
    __nv_bfloat16 l0 = __float2bfloat16(v.x - __bfloat162float(h0));
    __nv_bfloat16 l1 = __float2bfloat16(v.y - __bfloat162float(h1));
    hw = ((uint32_t)__bfloat16_as_ushort(h1) << 16) | __bfloat16_as_ushort(h0);
    lw = ((uint32_t)__bfloat16_as_ushort(l1) << 16) | __bfloat16_as_ushort(l0);
}
__device__ __forceinline__ void mma_bf16(float d[4],
                                         uint32_t a0, uint32_t a1, uint32_t a2, uint32_t a3,
                                         uint32_t b0, uint32_t b1) {
    asm volatile(
        "mma.sync.aligned.m16n8k16.row.col.f32.bf16.bf16.f32 "
        "{%0,%1,%2,%3}, {%4,%5,%6,%7}, {%8,%9}, {%0,%1,%2,%3};"
        : "+f"(d[0]), "+f"(d[1]), "+f"(d[2]), "+f"(d[3])
        : "r"(a0), "r"(a1), "r"(a2), "r"(a3), "r"(b0), "r"(b1));
}

// =======================================================================
// Phase-alternating fused kernel: 128 CTAs x 512 thr, 64 rows each.
// Per step: (a) ALL 16 warps: bf16-mma xg(t) (warp = m16 x n32);
//           (b) ALL 16 warps: R6 recurrence at 4 rows/warp.
// x(t+1) reg-prefetched under the mma; 2 __syncthreads per step.
// =======================================================================
#define NTHREADS 512
#define RSTB     336                        // plane row stride bytes
#define HPAD     68
#define SSTR     132                        // stage row stride (floats)

#define OFF_W0   0
#define OFF_W1   16384
#define OFF_W2   32768
#define OFF_WH   49152
#define OFF_WL   (OFF_WH + 128*RSTB)
#define OFF_XH   (OFF_WL + 128*RSTB)
#define OFF_XL   (OFF_XH + 64*RSTB)
#define OFF_H    (OFF_XL + 64*RSTB)
#define OFF_STG  (OFF_H + 2*HDIM*HPAD*4)
#define SMEM_BYTES (OFF_STG + 64*SSTR*4)    // 229376 B

// 512 threads: each loads 10 float2 (row = tid>>3, p = (tid&7)+8k)
__device__ __forceinline__ void load_x_regs(const float* __restrict__ xsrc,
                                            int t, int tid, float2 xr[10]) {
    const int r = tid >> 3, pb = tid & 7;
    const float* src = xsrc + (size_t)r * (T_STEPS * F_IN) + t * F_IN;
#pragma unroll
    for (int k = 0; k < 10; ++k) {
        int p = pb + 8 * k;
        xr[k] = (p < 79) ? *(const float2*)(src + 2 * p) : make_float2(0.f, 0.f);
    }
}
__device__ __forceinline__ void convert_x(char* Xh, char* Xl, int tid,
                                          const float2 xr[10]) {
    const int r = tid >> 3, pb = tid & 7;
#pragma unroll
    for (int k = 0; k < 10; ++k) {
        int p = pb + 8 * k;
        uint32_t hw, lw;
        split_pair(xr[k], hw, lw);
        int a = r * RSTB + 4 * p;
        *(uint32_t*)(Xh + a) = hw;
        *(uint32_t*)(Xl + a) = lw;
    }
}

__global__ void __launch_bounds__(NTHREADS, 1)
lstm_pa_kernel(const float* __restrict__ x,
               const float* __restrict__ Wih0, const float* __restrict__ Whh0,
               const float* __restrict__ Wih1, const float* __restrict__ Whh1,
               const float* __restrict__ W1,   const float* __restrict__ b1,
               const float* __restrict__ W2,   float* __restrict__ out) {
    extern __shared__ char sm[];
    float* sW0 = (float*)(sm + OFF_W0);
    float* sW1 = (float*)(sm + OFF_W1);
    float* sW2 = (float*)(sm + OFF_W2);
    char*  Wh  = sm + OFF_WH;
    char*  Wl  = sm + OFF_WL;
    char*  Xh  = sm + OFF_XH;
    char*  Xl  = sm + OFF_XL;
    float* h1  = (float*)(sm + OFF_H);
    float* h2  = h1 + HDIM * HPAD;
    float* stg = (float*)(sm + OFF_STG);

    const int tid = threadIdx.x;
    const int lane = tid & 31, w = tid >> 5;
    const int blk = blockIdx.x;
    const float* xsrc = x + (size_t)(blk * 64) * (T_STEPS * F_IN);

    // mma decomposition: warp = (mw = w&3) m16-tile x (nw = w>>2) n32-tile
    const int mw = w & 3, nw = w >> 2;
    const int g = lane >> 2, tq = lane & 3;
    const uint32_t aoff = (16 * mw + g) * RSTB + 4 * tq;
    // recurrence decomposition: warp w owns rows 4w..4w+3, lane = hidden unit j
    const int j = lane, m0 = w * 4;

    // ---- cooperative init ----
    for (int i = tid; i < HDIM * G4; i += NTHREADS) {
        int k = i >> 7, n = i & 127;
        sW0[i] = Whh0[n * HDIM + k];
        sW1[i] = Wih1[n * HDIM + k];
        sW2[i] = Whh1[n * HDIM + k];
    }
    for (int i = tid; i < 128 * 80; i += NTHREADS) {
        int n = i / 80, p = i - n * 80;
        uint32_t hw = 0, lw = 0;
        if (p < 79) {
            float2 v = *(const float2*)(Wih0 + n * F_IN + 2 * p);
            split_pair(v, hw, lw);
        }
        int a = n * RSTB + 4 * p;
        *(uint32_t*)(Wh + a) = hw;
        *(uint32_t*)(Wl + a) = lw;
    }
    for (int i = tid; i < 2 * HDIM * HPAD; i += NTHREADS) h1[i] = 0.0f;

    // prologue: x(0) -> regs -> planes
    float2 xr[10];
    load_x_regs(xsrc, 0, tid, xr);
    convert_x(Xh, Xl, tid, xr);
    __syncthreads();

    float c1[4] = {0.f, 0.f, 0.f, 0.f};
    float c2[4] = {0.f, 0.f, 0.f, 0.f};

    for (int t = 0; t < T_STEPS; ++t) {
        // prefetch x(t+1) (completes under the mma)
        if (t + 1 < T_STEPS) load_x_regs(xsrc, t + 1, tid, xr);

        // ===== phase (a): mma xg(t) = x(t) @ Wih0^T, warp m16 x n32 =====
        float acc[4][4];
#pragma unroll
        for (int nt = 0; nt < 4; ++nt)
#pragma unroll
            for (int q = 0; q < 4; ++q) acc[nt][q] = 0.0f;

#pragma unroll 2
        for (int ks = 0; ks < 10; ++ks) {
            const int kb = 32 * ks;
            uint32_t ah0 = *(const uint32_t*)(Xh + aoff + kb);
            uint32_t ah1 = *(const uint32_t*)(Xh + aoff + kb + 8 * RSTB);
            uint32_t ah2 = *(const uint32_t*)(Xh + aoff + kb + 16);
            uint32_t ah3 = *(const uint32_t*)(Xh + aoff + kb + 8 * RSTB + 16);
            uint32_t al0 = *(const uint32_t*)(Xl + aoff + kb);
            uint32_t al1 = *(const uint32_t*)(Xl + aoff + kb + 8 * RSTB);
            uint32_t al2 = *(const uint32_t*)(Xl + aoff + kb + 16);
            uint32_t al3 = *(const uint32_t*)(Xl + aoff + kb + 8 * RSTB + 16);
#pragma unroll
            for (int nt = 0; nt < 4; ++nt) {
                const uint32_t boff = (uint32_t)(32 * nw + 8 * nt + g) * RSTB + 4 * tq + kb;
                uint32_t bh0 = *(const uint32_t*)(Wh + boff);
                uint32_t bh1 = *(const uint32_t*)(Wh + boff + 16);
                uint32_t bl0 = *(const uint32_t*)(Wl + boff);
                uint32_t bl1 = *(const uint32_t*)(Wl + boff + 16);
                mma_bf16(acc[nt], ah0, ah1, ah2, ah3, bh0, bh1);
                mma_bf16(acc[nt], ah0, ah1, ah2, ah3, bl0, bl1);
                mma_bf16(acc[nt], al0, al1, al2, al3, bh0, bh1);
            }
        }
        __syncthreads();            // [A] all mma plane reads + prev recurrence done

        // stage D frags + convert x(t+1) planes
        {
            const int m = 16 * mw + g;
#pragma unroll
            for (int nt = 0; nt < 4; ++nt) {
                const int col = 32 * nw + 8 * nt + 2 * tq;
                *(float2*)(stg + (size_t)m * SSTR + col)
                    = make_float2(acc[nt][0], acc[nt][1]);
                *(float2*)(stg + (size_t)(m + 8) * SSTR + col)
                    = make_float2(acc[nt][2], acc[nt][3]);
            }
        }
        if (t + 1 < T_STEPS) convert_x(Xh, Xl, tid, xr);
        __syncthreads();            // [B] stage(t) + planes(t+1) ready

        // ===== phase (b): recurrence, 4 rows/warp =====
        u64 racc[4][2];             // [gate][rowpair], seeded with xg
#pragma unroll
        for (int gg = 0; gg < 4; ++gg)
#pragma unroll
            for (int p = 0; p < 2; ++p) {
                float a = stg[(m0 + 2 * p)     * SSTR + j + 32 * gg];
                float b = stg[(m0 + 2 * p + 1) * SSTR + j + 32 * gg];
                racc[gg][p] = pack2(a, b);
            }

        // layer 1: += h1 @ Whh0^T
#pragma unroll 8
        for (int k = 0; k < HDIM; ++k) {
            u64x2 ha = *(const u64x2*)(h1 + k * HPAD + m0);   // rows m0..m0+3
            const float* wk = sW0 + k * G4 + j;
#pragma unroll
            for (int gg = 0; gg < 4; ++gg) {
                u64 wv = pack2s(wk[32 * gg]);
                ffma2(racc[gg][0], ha.x, wv);
                ffma2(racc[gg][1], ha.y, wv);
            }
        }

        float hn[4];
#pragma unroll
        for (int p = 0; p < 2; ++p) {
            float2 iv = unpack2(racc[0][p]);
            float2 fv = unpack2(racc[1][p]);
            float2 gv = unpack2(racc[2][p]);
            float2 ov = unpack2(racc[3][p]);
            float ca = sigf(fv.x) * c1[2 * p]     + sigf(iv.x) * tanha(gv.x);
            float cb = sigf(fv.y) * c1[2 * p + 1] + sigf(iv.y) * tanha(gv.y);
            c1[2 * p] = ca; c1[2 * p + 1] = cb;
            hn[2 * p]     = sigf(ov.x) * tanha(ca);
            hn[2 * p + 1] = sigf(ov.y) * tanha(cb);
        }
        __syncwarp();
        *(float4*)(h1 + j * HPAD + m0) = make_float4(hn[0], hn[1], hn[2], hn[3]);
        __syncwarp();

        // layer 2: = h1_new @ Wih1^T + h2 @ Whh1^T
#pragma unroll
        for (int gg = 0; gg < 4; ++gg) { racc[gg][0] = 0ULL; racc[gg][1] = 0ULL; }

#pragma unroll 8
        for (int k = 0; k < HDIM; ++k) {
            u64x2 ha = *(const u64x2*)(h1 + k * HPAD + m0);
            u64x2 ga = *(const u64x2*)(h2 + k * HPAD + m0);
            const float* wka = sW1 + k * G4 + j;
            const float* wkb = sW2 + k * G4 + j;
#pragma unroll
            for (int gg = 0; gg < 4; ++gg) {
                u64 wa = pack2s(wka[32 * gg]);
                u64 wb = pack2s(wkb[32 * gg]);
                ffma2(racc[gg][0], ha.x, wa);
                ffma2(racc[gg][1], ha.y, wa);
                ffma2(racc[gg][0], ga.x, wb);
                ffma2(racc[gg][1], ga.y, wb);
            }
        }

#pragma unroll
        for (int p = 0; p < 2; ++p) {
            float2 iv = unpack2(racc[0][p]);
            float2 fv = unpack2(racc[1][p]);
            float2 gv = unpack2(racc[2][p]);
            float2 ov = unpack2(racc[3][p]);
            float ca = sigf(fv.x) * c2[2 * p]     + sigf(iv.x) * tanha(gv.x);
            float cb = sigf(fv.y) * c2[2 * p + 1] + sigf(iv.y) * tanha(gv.y);
            c2[2 * p] = ca; c2[2 * p + 1] = cb;
            hn[2 * p]     = sigf(ov.x) * tanha(ca);
            hn[2 * p + 1] = sigf(ov.y) * tanha(cb);
        }
        __syncwarp();
        *(float4*)(h2 + j * HPAD + m0) = make_float4(hn[0], hn[1], hn[2], hn[3]);
        __syncwarp();
        // next step's [A] barrier orders h/stage reuse
    }
    __syncthreads();

    // ---- epilogue: y = relu(c_n @ W1^T + b1) @ W2^T ----
    float* cs = stg;               // overlay [128 rows][33]
#pragma unroll
    for (int q = 0; q < 4; ++q) {
        cs[(m0 + q) * 33 + j]      = c1[q];
        cs[(64 + m0 + q) * 33 + j] = c2[q];
    }
    __syncthreads();

    if (tid < 128) {
        int L = tid >> 6, m = tid & 63;
        const float* crow = &cs[(L * 64 + m) * 33];
        float y = 0.0f;
#pragma unroll
        for (int u = 0; u < 16; ++u) {
            float s = __ldg(&b1[u]);
#pragma unroll
            for (int q = 0; q < 32; ++q) s += crow[q] * __ldg(&W1[u * 32 + q]);
            y += fmaxf(s, 0.0f) * __ldg(&W2[u]);
        }
        out[L * B_TOTAL + blk * 64 + m] = y;
    }
}

extern "C" void kernel_launch(void* const* d_in, const int* in_sizes, int n_in,
                              void* d_out, int out_size) {
    const float* x    = (const float*)d_in[0];
    const float* Wih0 = (const float*)d_in[1];
    const float* Whh0 = (const float*)d_in[2];
    const float* Wih1 = (const float*)d_in[3];
    const float* Whh1 = (const float*)d_in[4];
    const float* W1   = (const float*)d_in[5];
    const float* b1   = (const float*)d_in[6];
    const float* W2   = (const float*)d_in[7];
    float* out        = (float*)d_out;

    cudaFuncSetAttribute(lstm_pa_kernel,
                         cudaFuncAttributeMaxDynamicSharedMemorySize, SMEM_BYTES);
    lstm_pa_kernel<<<NBLK, NTHREADS, SMEM_BYTES>>>(x, Wih0, Whh0, Wih1, Whh1,
                                                   W1, b1, W2, out);
}

// round 17
// speedup vs baseline: 1.0177x; 1.0177x over previous
#include <cuda_runtime.h>
#include <cuda_bf16.h>
#include <stdint.h>
#include <math.h>

// Problem constants
#define B_TOTAL 8192
#define T_STEPS 60
#define F_IN    158
#define HDIM    32
#define G4      128
#define NBLK    128                        // 64-row blocks

typedef unsigned long long u64;
typedef ulonglong2 u64x2;

// xg scratch: [t][blk][m64][n128]  (252 MB)
__device__ __align__(256) float g_xg[(size_t)T_STEPS * NBLK * 64 * G4];
// per-block progress flags: g_flag[blk] = number of timesteps published
__device__ unsigned g_flag[NBLK];

// ---------------- helpers ----------------
__device__ __forceinline__ void ffma2(u64 &acc, u64 a, u64 b) {
    asm("fma.rn.f32x2 %0, %1, %2, %0;" : "+l"(acc) : "l"(a), "l"(b));
}
__device__ __forceinline__ u64 pack2(float x, float y) {
    u64 r; asm("mov.b64 %0, {%1, %2};" : "=l"(r) : "f"(x), "f"(y)); return r;
}
__device__ __forceinline__ u64 pack2s(float x) {
    u64 r; asm("mov.b64 %0, {%1, %1};" : "=l"(r) : "f"(x)); return r;
}
__device__ __forceinline__ float2 unpack2(u64 v) {
    float2 r; asm("mov.b64 {%0, %1}, %2;" : "=f"(r.x), "=f"(r.y) : "l"(v)); return r;
}
__device__ __forceinline__ float tanha(float x) {
    float y; asm("tanh.approx.f32 %0, %1;" : "=f"(y) : "f"(x)); return y;
}
__device__ __forceinline__ float sigf(float x) {      // 0.5*tanh(x/2)+0.5
    return fmaf(0.5f, tanha(0.5f * x), 0.5f);
}
__device__ __forceinline__ void split_pair(float2 v, uint32_t &hw, uint32_t &lw) {
    __nv_bfloat16 h0 = __float2bfloat16(v.x);
    __nv_bfloat16 h1 = __float2bfloat16(v.y);
    __nv_bfloat16 l0 = __float2bfloat16(v.x - __bfloat162float(h0));
    __nv_bfloat16 l1 = __float2bfloat16(v.y - __bfloat162float(h1));
    hw = ((uint32_t)__bfloat16_as_ushort(h1) << 16) | __bfloat16_as_ushort(h0);
    lw = ((uint32_t)__bfloat16_as_ushort(l1) << 16) | __bfloat16_as_ushort(l0);
}
__device__ __forceinline__ void mma_bf16(float d[4],
                                         uint32_t a0, uint32_t a1, uint32_t a2, uint32_t a3,
                                         uint32_t b0, uint32_t b1) {
    asm volatile(
        "mma.sync.aligned.m16n8k16.row.col.f32.bf16.bf16.f32 "
        "{%0,%1,%2,%3}, {%4,%5,%6,%7}, {%8,%9}, {%0,%1,%2,%3};"
        : "+f"(d[0]), "+f"(d[1]), "+f"(d[2]), "+f"(d[3])
        : "r"(a0), "r"(a1), "r"(a2), "r"(a3), "r"(b0), "r"(b1));
}

// =======================================================================
// Mixed-role kernel: 256 CTAs x 256 threads.
//   bid <  128 : CONSUMER  (exact R6 recurrence for rows bid*64..)
//   bid >= 128 : PRODUCER  (bf16-mma xg tiles for blk = bid-128, t order)
// Handshake: producer publishes g_flag[blk] = t+1 (release) after writing
// tile t; consumers spin with acquire loads. Flags zeroed by a memset node
// before this kernel in the same graph.
// =======================================================================
#define NTHREADS 256
#define RSTB     336                        // plane row stride bytes
#define HPAD     68
// producer smem: W planes + 32-row x planes
#define OFF_WH   0
#define OFF_WL   (OFF_WH + 128*RSTB)        // 43008
#define OFF_XH   (OFF_WL + 128*RSTB)        // 86016, [32][336B]
#define OFF_XL   (OFF_XH + 32*RSTB)         // 96768
#define SMEM_BYTES (OFF_XL + 32*RSTB)       // 107520 B
// consumer smem overlay (66560 B <= SMEM_BYTES)
#define B_SW  (HDIM * G4)

// producer: 256 threads load 10 float2 for one 32-row half
__device__ __forceinline__ void load_x32(const float* __restrict__ xsrc,
                                         int t, int half, int tid, float2 xr[10]) {
    const int r = tid >> 3, pb = tid & 7;          // r in 0..31
    const float* src = xsrc + (size_t)(half * 32 + r) * (T_STEPS * F_IN) + t * F_IN;
#pragma unroll
    for (int k = 0; k < 10; ++k) {
        int p = pb + 8 * k;
        xr[k] = (p < 79) ? *(const float2*)(src + 2 * p) : make_float2(0.f, 0.f);
    }
}
__device__ __forceinline__ void convert_x32(char* Xh, char* Xl, int tid,
                                            const float2 xr[10]) {
    const int r = tid >> 3, pb = tid & 7;
#pragma unroll
    for (int k = 0; k < 10; ++k) {
        int p = pb + 8 * k;
        uint32_t hw, lw;
        split_pair(xr[k], hw, lw);
        int a = r * RSTB + 4 * p;
        *(uint32_t*)(Xh + a) = hw;
        *(uint32_t*)(Xl + a) = lw;
    }
}

__global__ void __launch_bounds__(NTHREADS, 2)
lstm_olap_kernel(const float* __restrict__ x,
                 const float* __restrict__ Wih0, const float* __restrict__ Whh0,
                 const float* __restrict__ Wih1, const float* __restrict__ Whh1,
                 const float* __restrict__ W1,   const float* __restrict__ b1,
                 const float* __restrict__ W2,   float* __restrict__ out) {
    extern __shared__ char sm[];
    const int tid = threadIdx.x;
    const int lane = tid & 31, w = tid >> 5;

    if (blockIdx.x >= NBLK) {
        // ================= PRODUCER =================
        const int blk = blockIdx.x - NBLK;
        char* Wh = sm + OFF_WH;
        char* Wl = sm + OFF_WL;
        char* Xh = sm + OFF_XH;
        char* Xl = sm + OFF_XL;
        const float* xsrc = x + (size_t)(blk * 64) * (T_STEPS * F_IN);

        // Wih0 -> bf16 hi/lo planes
        for (int i = tid; i < 128 * 80; i += NTHREADS) {
            int n = i / 80, p = i - n * 80;
            uint32_t hw = 0, lw = 0;
            if (p < 79) {
                float2 v = *(const float2*)(Wih0 + n * F_IN + 2 * p);
                split_pair(v, hw, lw);
            }
            int a = n * RSTB + 4 * p;
            *(uint32_t*)(Wh + a) = hw;
            *(uint32_t*)(Wl + a) = lw;
        }

        // warp = (mw = w&1) m16 x (nw = w>>1) n32
        const int mw = w & 1, nw = w >> 1;
        const int g = lane >> 2, tq = lane & 3;
        const uint32_t aoff = (16 * mw + g) * RSTB + 4 * tq;

        float2 xr[10];
        load_x32(xsrc, 0, 0, tid, xr);
        convert_x32(Xh, Xl, tid, xr);
        __syncthreads();

        for (int it = 0; it < 2 * T_STEPS; ++it) {
            const int t = it >> 1, half = it & 1;
            const int nit = it + 1;
            if (nit < 2 * T_STEPS) load_x32(xsrc, nit >> 1, nit & 1, tid, xr);

            float acc[4][4];
#pragma unroll
            for (int nt = 0; nt < 4; ++nt)
#pragma unroll
                for (int q = 0; q < 4; ++q) acc[nt][q] = 0.0f;

#pragma unroll 2
            for (int ks = 0; ks < 10; ++ks) {
                const int kb = 32 * ks;
                uint32_t ah0 = *(const uint32_t*)(Xh + aoff + kb);
                uint32_t ah1 = *(const uint32_t*)(Xh + aoff + kb + 8 * RSTB);
                uint32_t ah2 = *(const uint32_t*)(Xh + aoff + kb + 16);
                uint32_t ah3 = *(const uint32_t*)(Xh + aoff + kb + 8 * RSTB + 16);
                uint32_t al0 = *(const uint32_t*)(Xl + aoff + kb);
                uint32_t al1 = *(const uint32_t*)(Xl + aoff + kb + 8 * RSTB);
                uint32_t al2 = *(const uint32_t*)(Xl + aoff + kb + 16);
                uint32_t al3 = *(const uint32_t*)(Xl + aoff + kb + 8 * RSTB + 16);
#pragma unroll
                for (int nt = 0; nt < 4; ++nt) {
                    const uint32_t boff = (uint32_t)(32 * nw + 8 * nt + g) * RSTB + 4 * tq + kb;
                    uint32_t bh0 = *(const uint32_t*)(Wh + boff);
                    uint32_t bh1 = *(const uint32_t*)(Wh + boff + 16);
                    uint32_t bl0 = *(const uint32_t*)(Wl + boff);
                    uint32_t bl1 = *(const uint32_t*)(Wl + boff + 16);
                    mma_bf16(acc[nt], ah0, ah1, ah2, ah3, bh0, bh1);
                    mma_bf16(acc[nt], ah0, ah1, ah2, ah3, bl0, bl1);
                    mma_bf16(acc[nt], al0, al1, al2, al3, bh0, bh1);
                }
            }

            // store frags -> g_xg[t][blk][half*32 + m][n]
            {
                const int m = half * 32 + 16 * mw + g;
                float* base = g_xg + ((size_t)t * NBLK + blk) * (64 * G4);
#pragma unroll
                for (int nt = 0; nt < 4; ++nt) {
                    const int col = 32 * nw + 8 * nt + 2 * tq;
                    *(float2*)(base + (size_t)m * G4 + col)
                        = make_float2(acc[nt][0], acc[nt][1]);
                    *(float2*)(base + (size_t)(m + 8) * G4 + col)
                        = make_float2(acc[nt][2], acc[nt][3]);
                }
            }
            __syncthreads();                 // tile stores + plane reads done
            if (half == 1 && tid == 0) {
                __threadfence();             // publish tile t
                asm volatile("st.global.release.gpu.u32 [%0], %1;"
                             :: "l"(&g_flag[blk]), "r"((unsigned)(t + 1)) : "memory");
            }
            if (nit < 2 * T_STEPS) convert_x32(Xh, Xl, tid, xr);
            __syncthreads();                 // planes for next half ready
        }
        return;
    }

    // ================= CONSUMER (exact R6 recurrence) =================
    const int blk = blockIdx.x;
    float* sW0 = (float*)sm;
    float* sW1 = sW0 + B_SW;
    float* sW2 = sW1 + B_SW;
    float* h1  = sW2 + B_SW;
    float* h2  = h1 + HDIM * HPAD;

    const int j = lane;
    const int m0 = w * 8;                    // 8 warps x 8 rows

    for (int i = tid; i < HDIM * G4; i += NTHREADS) {
        int k = i >> 7, n = i & 127;
        sW0[i] = Whh0[n * HDIM + k];
        sW1[i] = Wih1[n * HDIM + k];
        sW2[i] = Whh1[n * HDIM + k];
    }
    for (int i = tid; i < 2 * HDIM * HPAD; i += NTHREADS) h1[i] = 0.0f;
    __syncthreads();

    float c1[8], c2[8];
#pragma unroll
    for (int q = 0; q < 8; ++q) { c1[q] = 0.0f; c2[q] = 0.0f; }

    unsigned* flagp = &g_flag[blk];

    for (int t = 0; t < T_STEPS; ++t) {
        // wait for tile t (acquire)
        unsigned v;
        while (true) {
            asm volatile("ld.acquire.gpu.global.u32 %0, [%1];"
                         : "=r"(v) : "l"(flagp) : "memory");
            if (v > (unsigned)t) break;
            __nanosleep(64);
        }

        const float* xt = g_xg + ((size_t)t * NBLK + blk) * (64 * G4);
        float xr[4][8];                      // [gate][row]
#pragma unroll
        for (int g = 0; g < 4; ++g)
#pragma unroll
            for (int q = 0; q < 8; ++q)
                xr[g][q] = xt[(m0 + q) * G4 + j + 32 * g];

        // ---- layer 1: acc = h1 @ Whh0^T ----
        u64 acc[4][4];
#pragma unroll
        for (int g = 0; g < 4; ++g)
#pragma unroll
            for (int p = 0; p < 4; ++p) acc[g][p] = 0ULL;

#pragma unroll 4
        for (int k = 0; k < HDIM; ++k) {
            u64x2 ha = *(const u64x2*)(h1 + k * HPAD + m0);
            u64x2 hb = *(const u64x2*)(h1 + k * HPAD + m0 + 4);
            const float* wk = sW0 + k * G4 + j;
#pragma unroll
            for (int g = 0; g < 4; ++g) {
                u64 wv = pack2s(wk[32 * g]);
                ffma2(acc[g][0], ha.x, wv);
                ffma2(acc[g][1], ha.y, wv);
                ffma2(acc[g][2], hb.x, wv);
                ffma2(acc[g][3], hb.y, wv);
            }
        }

        float hn[8];
#pragma unroll
        for (int p = 0; p < 4; ++p) {
            float2 iv = unpack2(acc[0][p]);
            float2 fv = unpack2(acc[1][p]);
            float2 gv = unpack2(acc[2][p]);
            float2 ov = unpack2(acc[3][p]);
            iv.x += xr[0][2 * p]; iv.y += xr[0][2 * p + 1];
            fv.x += xr[1][2 * p]; fv.y += xr[1][2 * p + 1];
            gv.x += xr[2][2 * p]; gv.y += xr[2][2 * p + 1];
            ov.x += xr[3][2 * p]; ov.y += xr[3][2 * p + 1];
            float ca = sigf(fv.x) * c1[2 * p]     + sigf(iv.x) * tanha(gv.x);
            float cb = sigf(fv.y) * c1[2 * p + 1] + sigf(iv.y) * tanha(gv.y);
            c1[2 * p] = ca; c1[2 * p + 1] = cb;
            hn[2 * p]     = sigf(ov.x) * tanha(ca);
            hn[2 * p + 1] = sigf(ov.y) * tanha(cb);
        }
        __syncwarp();
        *(float4*)(h1 + j * HPAD + m0)     = make_float4(hn[0], hn[1], hn[2], hn[3]);
        *(float4*)(h1 + j * HPAD + m0 + 4) = make_float4(hn[4], hn[5], hn[6], hn[7]);
        __syncwarp();

        // ---- layer 2 ----
#pragma unroll
        for (int g = 0; g < 4; ++g)
#pragma unroll
            for (int p = 0; p < 4; ++p) acc[g][p] = 0ULL;

#pragma unroll 4
        for (int k = 0; k < HDIM; ++k) {
            u64x2 ha = *(const u64x2*)(h1 + k * HPAD + m0);
            u64x2 hb = *(const u64x2*)(h1 + k * HPAD + m0 + 4);
            u64x2 ga = *(const u64x2*)(h2 + k * HPAD + m0);
            u64x2 gb = *(const u64x2*)(h2 + k * HPAD + m0 + 4);
            const float* wka = sW1 + k * G4 + j;
            const float* wkb = sW2 + k * G4 + j;
#pragma unroll
            for (int g = 0; g < 4; ++g) {
                u64 wa = pack2s(wka[32 * g]);
                u64 wb = pack2s(wkb[32 * g]);
                ffma2(acc[g][0], ha.x, wa);
                ffma2(acc[g][1], ha.y, wa);
                ffma2(acc[g][2], hb.x, wa);
                ffma2(acc[g][3], hb.y, wa);
                ffma2(acc[g][0], ga.x, wb);
                ffma2(acc[g][1], ga.y, wb);
                ffma2(acc[g][2], gb.x, wb);
                ffma2(acc[g][3], gb.y, wb);
            }
        }

#pragma unroll
        for (int p = 0; p < 4; ++p) {
            float2 iv = unpack2(acc[0][p]);
            float2 fv = unpack2(acc[1][p]);
            float2 gv = unpack2(acc[2][p]);
            float2 ov = unpack2(acc[3][p]);
            float ca = sigf(fv.x) * c2[2 * p]     + sigf(iv.x) * tanha(gv.x);
            float cb = sigf(fv.y) * c2[2 * p + 1] + sigf(iv.y) * tanha(gv.y);
            c2[2 * p] = ca; c2[2 * p + 1] = cb;
            hn[2 * p]     = sigf(ov.x) * tanha(ca);
            hn[2 * p + 1] = sigf(ov.y) * tanha(cb);
        }
        __syncwarp();
        *(float4*)(h2 + j * HPAD + m0)     = make_float4(hn[0], hn[1], hn[2], hn[3]);
        *(float4*)(h2 + j * HPAD + m0 + 4) = make_float4(hn[4], hn[5], hn[6], hn[7]);
        __syncwarp();
    }
    __syncthreads();

    // ---- epilogue ----
    float* cs = (float*)sm;                  // overlay on weights
#pragma unroll
    for (int q = 0; q < 8; ++q) {
        cs[(m0 + q) * 33 + j]      = c1[q];
        cs[(64 + m0 + q) * 33 + j] = c2[q];
    }
    __syncthreads();

    if (tid < 128) {
        int L = tid >> 6, m = tid & 63;
        const float* crow = &cs[(L * 64 + m) * 33];
        float y = 0.0f;
#pragma unroll
        for (int u = 0; u < 16; ++u) {
            float s = __ldg(&b1[u]);
#pragma unroll
            for (int q = 0; q < 32; ++q) s += crow[q] * __ldg(&W1[u * 32 + q]);
            y += fmaxf(s, 0.0f) * __ldg(&W2[u]);
        }
        out[L * B_TOTAL + blk * 64 + m] = y;
    }
}

extern "C" void kernel_launch(void* const* d_in, const int* in_sizes, int n_in,
                              void* d_out, int out_size) {
    const float* x    = (const float*)d_in[0];
    const float* Wih0 = (const float*)d_in[1];
    const float* Whh0 = (const float*)d_in[2];
    const float* Wih1 = (const float*)d_in[3];
    const float* Whh1 = (const float*)d_in[4];
    const float* W1   = (const float*)d_in[5];
    const float* b1   = (const float*)d_in[6];
    const float* W2   = (const float*)d_in[7];
    float* out        = (float*)d_out;

    // zero the progress flags (graph-captured memset node, runs every replay)
    void* flag_ptr = nullptr;
    cudaGetSymbolAddress(&flag_ptr, g_flag);
    cudaMemsetAsync(flag_ptr, 0, NBLK * sizeof(unsigned));

    cudaFuncSetAttribute(lstm_olap_kernel,
                         cudaFuncAttributeMaxDynamicSharedMemorySize, SMEM_BYTES);
    lstm_olap_kernel<<<2 * NBLK, NTHREADS, SMEM_BYTES>>>(x, Wih0, Whh0, Wih1, Whh1,
                                                         W1, b1, W2, out);
}